// round 3
// baseline (speedup 1.0000x reference)
#include <cuda_runtime.h>
#include <cstdint>
#include <cstddef>

#define T_TOTAL 524288
#define IN_LEN  64
#define HID     128
#define NMEM    64
#define OUT_LEN 32
#define NCHUNK  1024
#define CHUNK_L 512
#define TILE_R  64
#define NTILES  (CHUNK_L / TILE_R)

// x tile transposed pitch (odd-ish to dodge bank conflicts, even for LDS.64 align)
#define XP 66
// z tile pitch
#define ZP 65

// ---- scratch (static __device__ arrays: allowed; no runtime alloc) ----
__device__ __align__(16) float g_a[(size_t)T_TOTAL * NMEM];
__device__ __align__(16) float g_b[(size_t)T_TOTAL * NMEM];
__device__ __align__(16) float g_Ac[NCHUNK * NMEM];
__device__ __align__(16) float g_Bc[NCHUNK * NMEM];
__device__ __align__(16) float g_U [NCHUNK * NMEM];

typedef unsigned long long u64;

__device__ __forceinline__ u64 pk2(float lo, float hi) {
    u64 r; asm("mov.b64 %0, {%1,%2};" : "=l"(r) : "f"(lo), "f"(hi)); return r;
}
__device__ __forceinline__ float2 upk(u64 v) {
    float2 r; asm("mov.b64 {%0,%1}, %2;" : "=f"(r.x), "=f"(r.y) : "l"(v)); return r;
}
// packed fp32x2 FMA: d.lo += a.lo*b.lo ; d.hi += a.hi*b.hi  (Blackwell FFMA2)
__device__ __forceinline__ void ffma2(u64 &d, u64 a, u64 b) {
    asm("fma.rn.f32x2 %0, %1, %2, %0;" : "+l"(d) : "l"(a), "l"(b));
}
__device__ __forceinline__ float sigf(float x) {
    float e = __expf(-x);
    return __fdividef(1.0f, 1.0f + e);
}

// ============================================================================
// Kernel 1: GEMM1 (inputs@W1+B1) + sigmoid + gate -> (a,b) to scratch,
//           plus per-chunk affine composition (A,B).
// grid = NCHUNK blocks, 256 threads; chunk = 512 rows in 8 tiles of 64.
// ============================================================================
__global__ __launch_bounds__(256, 2)
void k1_gemm1_compose(const float* __restrict__ inp,
                      const float* __restrict__ W1,
                      const float* __restrict__ B1) {
    extern __shared__ float sm[];
    float* W1s = sm;                       // 8192
    float* B1s = W1s + HID * IN_LEN;       // 128
    float* xs  = B1s + HID;                // 64*XP = 4224 (transposed x tile [k][r])
    float* aa  = xs + TILE_R * XP;         // 4096
    float* bb  = aa + TILE_R * NMEM;       // 4096

    const int tid = threadIdx.x;
    const int c   = blockIdx.x;

    // load W1 ([k][c] row-major, matches input layout) and B1
    {
        const float4* src = (const float4*)W1;
        float4*       dst = (float4*)W1s;
        #pragma unroll
        for (int i = tid; i < HID * IN_LEN / 4; i += 256) dst[i] = src[i];
        if (tid < HID) B1s[tid] = B1[tid];
    }

    float Av = 1.0f, Bv = 0.0f;            // chunk composition state (threads 0..63)
    const int ci = tid & 31;               // channel group: left 2ci,2ci+1 ; right 64+2ci,..
    const int ri = tid >> 5;               // row group: rows 8ri..8ri+7
    const int kcol = tid & 63;             // for transpose load
    const int rq   = tid >> 6;

    __syncthreads();

    for (int tt = 0; tt < NTILES; tt++) {
        const int t0 = c * CHUNK_L + tt * TILE_R;

        // transpose-load x rows [t0, t0+64) into xs[k*XP + r]
        #pragma unroll
        for (int rr = 0; rr < 16; rr++) {
            int r = rq + rr * 4;
            xs[kcol * XP + r] = inp[(size_t)(t0 + r) * IN_LEN + kcol];
        }
        __syncthreads();

        // register-tiled GEMM1: 8 rows (4 packed row-pairs) x 4 channels per thread
        u64 z2 = pk2(0.0f, 0.0f);
        u64 aL0[4], aL1[4], aR0[4], aR1[4];
        #pragma unroll
        for (int p = 0; p < 4; p++) { aL0[p]=z2; aL1[p]=z2; aR0[p]=z2; aR1[p]=z2; }

        const float* xb = xs + ri * 8;
        #pragma unroll 8
        for (int k = 0; k < IN_LEN; k++) {
            u64 x01 = *(const u64*)(xb + k * XP + 0);
            u64 x23 = *(const u64*)(xb + k * XP + 2);
            u64 x45 = *(const u64*)(xb + k * XP + 4);
            u64 x67 = *(const u64*)(xb + k * XP + 6);
            float2 wl = *(const float2*)(W1s + k * HID + 2 * ci);
            float2 wr = *(const float2*)(W1s + k * HID + 64 + 2 * ci);
            u64 wl0 = pk2(wl.x, wl.x), wl1 = pk2(wl.y, wl.y);
            u64 wr0 = pk2(wr.x, wr.x), wr1 = pk2(wr.y, wr.y);
            ffma2(aL0[0], x01, wl0); ffma2(aL0[1], x23, wl0);
            ffma2(aL0[2], x45, wl0); ffma2(aL0[3], x67, wl0);
            ffma2(aL1[0], x01, wl1); ffma2(aL1[1], x23, wl1);
            ffma2(aL1[2], x45, wl1); ffma2(aL1[3], x67, wl1);
            ffma2(aR0[0], x01, wr0); ffma2(aR0[1], x23, wr0);
            ffma2(aR0[2], x45, wr0); ffma2(aR0[3], x67, wr0);
            ffma2(aR1[0], x01, wr1); ffma2(aR1[1], x23, wr1);
            ffma2(aR1[2], x45, wr1); ffma2(aR1[3], x67, wr1);
        }

        // epilogue: sigmoid, gate -> a,b ; store to global scratch + smem tile
        {
            const float bl0 = B1s[2*ci], bl1 = B1s[2*ci+1];
            const float br0 = B1s[64+2*ci], br1 = B1s[64+2*ci+1];
            #pragma unroll
            for (int p = 0; p < 4; p++) {
                float2 L0 = upk(aL0[p]), L1 = upk(aL1[p]);
                float2 R0 = upk(aR0[p]), R1 = upk(aR1[p]);
                #pragma unroll
                for (int e = 0; e < 2; e++) {
                    int r = 8 * ri + 2 * p + e;
                    float l0 = sigf((e ? L0.y : L0.x) + bl0);
                    float l1 = sigf((e ? L1.y : L1.x) + bl1);
                    float r0 = sigf((e ? R0.y : R0.x) + br0);
                    float r1 = sigf((e ? R1.y : R1.x) + br1);
                    float a0 = l0 * r0, a1 = l1 * r1;
                    float b0 = 1.0f - l0, b1 = 1.0f - l1;
                    size_t gi = (size_t)(t0 + r) * NMEM + 2 * ci;
                    *(float2*)(g_a + gi) = make_float2(a0, a1);
                    *(float2*)(g_b + gi) = make_float2(b0, b1);
                    *(float2*)(aa + r * NMEM + 2 * ci) = make_float2(a0, a1);
                    *(float2*)(bb + r * NMEM + 2 * ci) = make_float2(b0, b1);
                }
            }
        }
        __syncthreads();

        // per-chunk affine composition (time order): (A,B) <- (a*A, a*B + b)
        if (tid < NMEM) {
            #pragma unroll 8
            for (int r = 0; r < TILE_R; r++) {
                float a = aa[r * NMEM + tid];
                float b = bb[r * NMEM + tid];
                Bv = fmaf(a, Bv, b);
                Av = Av * a;
            }
        }
        __syncthreads();
    }

    if (tid < NMEM) {
        g_Ac[c * NMEM + tid] = Av;
        g_Bc[c * NMEM + tid] = Bv;
    }
}

// ============================================================================
// Kernel 2: sequential prefix over 1024 chunks -> u at each chunk start.
// ============================================================================
__global__ void k2_chunk_scan() {
    const int j = threadIdx.x;   // 64 threads, one channel each
    float u = 0.0f;
    #pragma unroll 4
    for (int cc = 0; cc < NCHUNK; cc++) {
        g_U[cc * NMEM + j] = u;
        u = fmaf(g_Ac[cc * NMEM + j], u, g_Bc[cc * NMEM + j]);
    }
}

// ============================================================================
// Kernel 3: per chunk, replay recurrence from (a,b) scratch and fuse GEMM2.
// z[t0+r+1] = u after step t0+r ; out = z@W2 + B2 ; out[0] = B2.
// ============================================================================
__global__ __launch_bounds__(256, 3)
void k3_scan_gemm2(const float* __restrict__ W2,
                   const float* __restrict__ B2,
                   float* __restrict__ out) {
    extern __shared__ float sm[];
    float* W2s = sm;                         // 2048
    float* B2s = W2s + NMEM * OUT_LEN;       // 32
    float* as_ = B2s + OUT_LEN;              // 4096
    float* bs_ = as_ + TILE_R * NMEM;        // 4096
    float* zs  = bs_ + TILE_R * NMEM;        // 64*ZP = 4160

    const int tid = threadIdx.x;
    const int c   = blockIdx.x;

    #pragma unroll
    for (int i = tid; i < NMEM * OUT_LEN / 4; i += 256)
        ((float4*)W2s)[i] = ((const float4*)W2)[i];
    if (tid < OUT_LEN) B2s[tid] = B2[tid];
    if (c == 0 && tid < OUT_LEN) out[tid] = B2[tid];   // row 0: z=0 -> out=B2

    float u = 0.0f;
    if (tid < NMEM) u = g_U[c * NMEM + tid];

    const int oc2 = tid & 15;   // out channel pair 2*oc2
    const int rg  = tid >> 4;   // 16 groups x 4 rows
    __syncthreads();

    for (int tt = 0; tt < NTILES; tt++) {
        const int t0 = c * CHUNK_L + tt * TILE_R;

        // stage a,b tile into smem (coalesced float4)
        {
            const float4* sa = (const float4*)(g_a + (size_t)t0 * NMEM);
            const float4* sb = (const float4*)(g_b + (size_t)t0 * NMEM);
            float4* da = (float4*)as_;
            float4* db = (float4*)bs_;
            #pragma unroll
            for (int i = 0; i < 4; i++) {
                da[tid + i * 256] = sa[tid + i * 256];
                db[tid + i * 256] = sb[tid + i * 256];
            }
        }
        __syncthreads();

        // sequential replay within tile (threads 0..63, one channel each)
        if (tid < NMEM) {
            #pragma unroll 8
            for (int r = 0; r < TILE_R; r++) {
                u = fmaf(as_[r * NMEM + tid], u, bs_[r * NMEM + tid]);
                zs[r * ZP + tid] = u;     // z row (t0 + r + 1)
            }
        }
        __syncthreads();

        // GEMM2: 4 rows x 2 out-channels per thread, packed FFMA2
        u64 acc0 = pk2(B2s[2 * oc2], B2s[2 * oc2 + 1]);
        u64 acc1 = acc0, acc2 = acc0, acc3 = acc0;
        const float* zrow = zs + rg * 4 * ZP;
        #pragma unroll 16
        for (int k = 0; k < NMEM; k++) {
            u64 wp = *(const u64*)(W2s + k * OUT_LEN + 2 * oc2);
            float z0 = zrow[k];
            float z1 = zrow[ZP + k];
            float z2 = zrow[2 * ZP + k];
            float z3 = zrow[3 * ZP + k];
            ffma2(acc0, pk2(z0, z0), wp);
            ffma2(acc1, pk2(z1, z1), wp);
            ffma2(acc2, pk2(z2, z2), wp);
            ffma2(acc3, pk2(z3, z3), wp);
        }
        #pragma unroll
        for (int i = 0; i < 4; i++) {
            int t = t0 + 1 + rg * 4 + i;
            if (t < T_TOTAL) {
                u64 a = (i == 0) ? acc0 : (i == 1) ? acc1 : (i == 2) ? acc2 : acc3;
                float2 v = upk(a);
                *(float2*)(out + (size_t)t * OUT_LEN + 2 * oc2) = v;
            }
        }
        __syncthreads();
    }
}

// ============================================================================
// launch
// ============================================================================
extern "C" void kernel_launch(void* const* d_in, const int* in_sizes, int n_in,
                              void* d_out, int out_size) {
    const float* inp = (const float*)d_in[0];
    const float* W1  = (const float*)d_in[1];
    const float* B1  = (const float*)d_in[2];
    const float* W2  = (const float*)d_in[3];
    const float* B2  = (const float*)d_in[4];
    float* out = (float*)d_out;

    const int smem1 = (HID * IN_LEN + HID + TILE_R * XP + 2 * TILE_R * NMEM) * 4; // 82944 B
    const int smem3 = (NMEM * OUT_LEN + OUT_LEN + 2 * TILE_R * NMEM + TILE_R * ZP) * 4; // 57728 B

    cudaFuncSetAttribute(k1_gemm1_compose, cudaFuncAttributeMaxDynamicSharedMemorySize, smem1);
    cudaFuncSetAttribute(k3_scan_gemm2,    cudaFuncAttributeMaxDynamicSharedMemorySize, smem3);

    k1_gemm1_compose<<<NCHUNK, 256, smem1>>>(inp, W1, B1);
    k2_chunk_scan<<<1, NMEM>>>();
    k3_scan_gemm2<<<NCHUNK, 256, smem3>>>(W2, B2, out);
    (void)in_sizes; (void)n_in; (void)out_size;
}